// round 8
// baseline (speedup 1.0000x reference)
#include <cuda_runtime.h>

#define NB 4
#define NXg 432
#define NYg 496
#define Hc 248
#define Wc 216
#define HW (Hc*Wc)            // 53568
#define C1 8
#define C2 16
#define COUT 400
#define CSP 384
#define KS 15
#define RAD 7
#define NBN (NB*HW)
#define GTOT (NB*NYg*NXg)     // 857088

#define NCHAIN 384
#define NCOPY  208
#define GRID   (NCHAIN+NCOPY) // 592 blocks <= 148 SMs * 4
#define TPB    256
#define NT     (NCHAIN*TPB)   // 98304 chain threads

#define COPY_N (NB*CSP*HW/4)  // 20,570,112 float4
#define PER_B  (CSP*HW/4)     // 5,142,528
#define DSKIP  ((COUT-CSP)*HW/4) // 214,272
#define CTH    (NCOPY*TPB)    // 53,248 copy threads

// conv tiling: HW = 53568 = 12*4464 = 6*8928
#define SEG1 12
#define PX1  4464
#define SEG2 6
#define PX2  8928

// scratch
__device__ float g_hist[GTOT];
__device__ float g_tmp [GTOT];
__device__ float g_dm  [NB*HW];
__device__ float g_c1  [NB*C1*HW];
__device__ float g_c2  [NB*C2*HW];
__device__ float g_gauss[KS];
__device__ int   g_max[NB];
__device__ float g_stats1[2*C1];
__device__ float g_stats2[2*C2];
// barrier state (self-restoring: even # of barriers per launch)
__device__ int          g_cnt;
__device__ volatile int g_sense;

// jax.image.resize 'linear' antialias=True, 2x down: taps [1,3,3,1]/8, edge-renormalized
__device__ __forceinline__ void taps4(int i, int n, int* j, float* w) {
    const float base[4] = {1.f, 3.f, 3.f, 1.f};
    float s = 0.f;
    #pragma unroll
    for (int k = 0; k < 4; k++) {
        int jj = 2*i - 1 + k;
        j[k] = jj;
        if (jj >= 0 && jj < n) { w[k] = base[k]; s += base[k]; }
        else w[k] = 0.f;
    }
    #pragma unroll
    for (int k = 0; k < 4; k++) w[k] /= s;
}

__global__ void __launch_bounds__(TPB, 4)
k_all(const float* __restrict__ pts, int npts,
      const float* __restrict__ w1, const float* __restrict__ gamma1, const float* __restrict__ beta1,
      const float* __restrict__ w2, const float* __restrict__ gamma2, const float* __restrict__ beta2,
      const float4* __restrict__ csrc, float4* __restrict__ cdst, float* __restrict__ out)
{
    const int bid = blockIdx.x;

    // ---------------- copy blocks: stream the 384-channel concat, fully concurrent ----
    if (bid >= NCHAIN) {
        int t = (bid - NCHAIN)*TPB + threadIdx.x;       // 0..CTH-1
        for (int i = t; i < COPY_N; i += 4*CTH) {
            int i0 = i, i1 = i + CTH, i2 = i + 2*CTH, i3 = i + 3*CTH;
            float4 v0, v1, v2, v3;
            bool p1 = i1 < COPY_N, p2 = i2 < COPY_N, p3 = i3 < COPY_N;
            v0 = __ldcs(csrc + i0);
            if (p1) v1 = __ldcs(csrc + i1);
            if (p2) v2 = __ldcs(csrc + i2);
            if (p3) v3 = __ldcs(csrc + i3);
            __stcs(cdst + i0 + (i0/PER_B)*DSKIP, v0);
            if (p1) __stcs(cdst + i1 + (i1/PER_B)*DSKIP, v1);
            if (p2) __stcs(cdst + i2 + (i2/PER_B)*DSKIP, v2);
            if (p3) __stcs(cdst + i3 + (i3/PER_B)*DSKIP, v3);
        }
        return;
    }

    // ---------------- chain blocks ----------------
    __shared__ float sm1[TPB], sm2[TPB];
    __shared__ float ws[C1*9];
    __shared__ float sA[C2], sB[C2];
    __shared__ int   lsense;
    if (threadIdx.x == 0) lsense = 0;
    __syncthreads();

    auto gbar = [&]() {
        __syncthreads();
        if (threadIdx.x == 0) {
            int s = lsense ^ 1; lsense = s;
            __threadfence();
            if (atomicAdd(&g_cnt, 1) == NCHAIN - 1) {
                g_cnt = 0;
                g_sense = s;
            } else {
                while (g_sense != s) __nanosleep(64);
            }
            __threadfence();
        }
        __syncthreads();
    };

    const int t = bid*TPB + threadIdx.x;                // 0..NT-1

    // ---- s0: zero hist/stats/max, gaussian weights ----
    for (int i = t; i < GTOT; i += NT) g_hist[i] = 0.f;
    if (t < KS) {
        const float sig = 6.25f;
        float s = 0.f;
        for (int k = 0; k < KS; k++) {
            float c = (float)(k - RAD);
            s += expf(-c*c/(2.f*sig*sig));
        }
        float c = (float)(t - RAD);
        g_gauss[t] = expf(-c*c/(2.f*sig*sig)) / s;
    }
    if (t < NB)   g_max[t] = 0;
    if (t < 2*C1) g_stats1[t] = 0.f;
    if (t < 2*C2) g_stats2[t] = 0.f;
    gbar(); // 1

    // ---- s1: histogram ----
    for (int i = t; i < npts; i += NT) {
        const float* p = pts + (size_t)i*5;
        int b = (int)p[0];
        int x = (int)__fdiv_rn(p[1] - 0.0f,  0.16f);
        int y = (int)__fdiv_rn(p[2] + 39.68f, 0.16f);
        x = min(max(x, 0), NXg-1);
        y = min(max(y, 0), NYg-1);
        atomicAdd(&g_hist[(b*NYg + y)*NXg + x], 1.0f);
    }
    gbar(); // 2

    // ---- s2: blur x ----
    for (int i = t; i < GTOT; i += NT) {
        int x = i % NXg;
        int row = i / NXg;
        float acc = 0.f;
        #pragma unroll
        for (int k = 0; k < KS; k++) {
            int xx = x + k - RAD;
            if (xx >= 0 && xx < NXg)
                acc += g_gauss[k] * g_hist[row*NXg + xx];
        }
        g_tmp[i] = acc;
    }
    gbar(); // 3

    // ---- s3: blur y + per-batch max ----
    {
        float m0 = 0.f, m1 = 0.f, m2 = 0.f, m3 = 0.f;
        for (int i = t; i < GTOT; i += NT) {
            int x = i % NXg;
            int y = (i / NXg) % NYg;
            int b = i / (NXg*NYg);
            float acc = 0.f;
            #pragma unroll
            for (int k = 0; k < KS; k++) {
                int yy = y + k - RAD;
                if (yy >= 0 && yy < NYg)
                    acc += g_gauss[k] * g_tmp[(b*NYg + yy)*NXg + x];
            }
            g_hist[i] = acc;
            m0 = (b == 0) ? fmaxf(m0, acc) : m0;
            m1 = (b == 1) ? fmaxf(m1, acc) : m1;
            m2 = (b == 2) ? fmaxf(m2, acc) : m2;
            m3 = (b == 3) ? fmaxf(m3, acc) : m3;
        }
        #pragma unroll
        for (int bb = 0; bb < NB; bb++) {
            float mv = (bb == 0) ? m0 : (bb == 1) ? m1 : (bb == 2) ? m2 : m3;
            sm1[threadIdx.x] = mv; __syncthreads();
            for (int s = TPB/2; s > 0; s >>= 1) {
                if (threadIdx.x < s) sm1[threadIdx.x] = fmaxf(sm1[threadIdx.x], sm1[threadIdx.x+s]);
                __syncthreads();
            }
            if (threadIdx.x == 0 && sm1[0] > 0.f) atomicMax(&g_max[bb], __float_as_int(sm1[0]));
            __syncthreads();
        }
    }
    gbar(); // 4

    // ---- s4: antialiased bilinear 2x downsample + normalize ----
    for (int i = t; i < NB*HW; i += NT) {
        int x = i % Wc;
        int y = (i / Wc) % Hc;
        int b = i / HW;
        int jy[4], jx[4]; float wy[4], wx[4];
        taps4(y, NYg, jy, wy);
        taps4(x, NXg, jx, wx);
        float acc = 0.f;
        #pragma unroll
        for (int a = 0; a < 4; a++) {
            if (wy[a] != 0.f) {
                float r = 0.f;
                #pragma unroll
                for (int c = 0; c < 4; c++)
                    if (wx[c] != 0.f)
                        r += wx[c] * g_hist[(b*NYg + jy[a])*NXg + jx[c]];
                acc += wy[a] * r;
            }
        }
        float mx = __int_as_float(g_max[b]);
        g_dm[i] = (mx > 0.f) ? acc / mx : acc;
    }
    gbar(); // 5

    // ---- s5: conv1 (1->8) + stats1, one tile per block (384 tiles) ----
    {
        int bc = bid / SEG1, seg = bid % SEG1;  // bc = b*C1+c
        int b = bc / C1, c = bc % C1;
        const float* wp = w1 + c*9;
        const float* in = g_dm + b*HW;
        float ls = 0.f, ls2 = 0.f;
        int p0 = seg*PX1, p1 = p0 + PX1;
        for (int p = p0 + threadIdx.x; p < p1; p += TPB) {
            int x = p % Wc, y = p / Wc;
            float v = 0.f;
            #pragma unroll
            for (int dy = 0; dy < 3; dy++) {
                int yy = y + dy - 1;
                if (yy < 0 || yy >= Hc) continue;
                #pragma unroll
                for (int dx = 0; dx < 3; dx++) {
                    int xx = x + dx - 1;
                    if (xx < 0 || xx >= Wc) continue;
                    v = fmaf(__ldg(&wp[dy*3+dx]), in[yy*Wc+xx], v);
                }
            }
            g_c1[bc*HW + p] = v;
            ls += v; ls2 += v*v;
        }
        sm1[threadIdx.x] = ls; sm2[threadIdx.x] = ls2; __syncthreads();
        for (int s = TPB/2; s > 0; s >>= 1) {
            if (threadIdx.x < s) { sm1[threadIdx.x] += sm1[threadIdx.x+s]; sm2[threadIdx.x] += sm2[threadIdx.x+s]; }
            __syncthreads();
        }
        if (threadIdx.x == 0) {
            atomicAdd(&g_stats1[c],      sm1[0]);
            atomicAdd(&g_stats1[C1 + c], sm2[0]);
        }
    }
    gbar(); // 6

    // ---- s6: conv2 (8->16) with inline BN1+ReLU + stats2, one tile per block ----
    {
        int bc = bid / SEG2, seg = bid % SEG2;  // bc = b*C2+co
        int b = bc / C2, co = bc % C2;
        if (threadIdx.x < C1*9) ws[threadIdx.x] = w2[co*C1*9 + threadIdx.x];
        if (threadIdx.x < C1) {
            int c = threadIdx.x;
            float mean = g_stats1[c] / (float)NBN;
            float var  = g_stats1[C1+c] / (float)NBN - mean*mean;
            float s    = gamma1[c] * rsqrtf(var + 1e-3f);
            sA[c] = s; sB[c] = beta1[c] - mean*s;
        }
        __syncthreads();
        float ls = 0.f, ls2 = 0.f;
        int p0 = seg*PX2, p1 = p0 + PX2;
        for (int p = p0 + threadIdx.x; p < p1; p += TPB) {
            int x = p % Wc, y = p / Wc;
            float v = 0.f;
            #pragma unroll
            for (int ci = 0; ci < C1; ci++) {
                const float* in = g_c1 + (b*C1 + ci)*HW;
                const float* wp = ws + ci*9;
                float a = sA[ci], s0 = sB[ci];
                #pragma unroll
                for (int dy = 0; dy < 3; dy++) {
                    int yy = y + dy - 1;
                    if (yy < 0 || yy >= Hc) continue;
                    #pragma unroll
                    for (int dx = 0; dx < 3; dx++) {
                        int xx = x + dx - 1;
                        if (xx < 0 || xx >= Wc) continue;
                        float tv = fmaxf(fmaf(in[yy*Wc+xx], a, s0), 0.f);
                        v = fmaf(wp[dy*3+dx], tv, v);
                    }
                }
            }
            g_c2[bc*HW + p] = v;
            ls += v; ls2 += v*v;
        }
        sm1[threadIdx.x] = ls; sm2[threadIdx.x] = ls2; __syncthreads();
        for (int s = TPB/2; s > 0; s >>= 1) {
            if (threadIdx.x < s) { sm1[threadIdx.x] += sm1[threadIdx.x+s]; sm2[threadIdx.x] += sm2[threadIdx.x+s]; }
            __syncthreads();
        }
        if (threadIdx.x == 0) {
            atomicAdd(&g_stats2[co],      sm1[0]);
            atomicAdd(&g_stats2[C2 + co], sm2[0]);
        }
    }
    gbar(); // 7

    // ---- s7: BN2 + relu + scatter into concat slot ----
    {
        if (threadIdx.x < C2) {
            int c = threadIdx.x;
            float mean = g_stats2[c] / (float)NBN;
            float var  = g_stats2[C2+c] / (float)NBN - mean*mean;
            float s    = gamma2[c] * rsqrtf(var + 1e-3f);
            sA[c] = s; sB[c] = beta2[c] - mean*s;
        }
        __syncthreads();
        for (int i = t; i < NB*C2*HW; i += NT) {
            int hw = i % HW;
            int c  = (i / HW) % C2;
            int b  = i / (C2*HW);
            float v = fmaxf(fmaf(g_c2[i], sA[c], sB[c]), 0.f);
            out[((size_t)b*COUT + CSP + c)*HW + hw] = v;
        }
    }
    gbar(); // 8 (dummy: keeps barrier count even so sense/counter self-restore per launch)
}

extern "C" void kernel_launch(void* const* d_in, const int* in_sizes, int n_in,
                              void* d_out, int out_size) {
    const float* spatial = (const float*)d_in[0];
    const float* points  = (const float*)d_in[1];
    const float* w1      = (const float*)d_in[2];
    const float* gamma1  = (const float*)d_in[3];
    const float* beta1   = (const float*)d_in[4];
    const float* w2      = (const float*)d_in[5];
    const float* gamma2  = (const float*)d_in[6];
    const float* beta2   = (const float*)d_in[7];
    float* out = (float*)d_out;
    int npts = in_sizes[1] / 5;

    k_all<<<GRID, TPB>>>(points, npts, w1, gamma1, beta1, w2, gamma2, beta2,
                         (const float4*)spatial, (float4*)out, out);
}

// round 9
// speedup vs baseline: 1.3889x; 1.3889x over previous
#include <cuda_runtime.h>

#define NB 4
#define NXg 432
#define NYg 496
#define Hc 248
#define Wc 216
#define HW (Hc*Wc)
#define C1 8
#define C2 16
#define COUT 400
#define CSP 384
#define KS 15
#define RAD 7
#define NBN (NB*HW)
#define GTOT (NB*NYg*NXg)

// scratch (device globals; zero-initialized at load)
__device__ float g_hist[GTOT];
__device__ float g_tmp [GTOT];
__device__ float g_dm  [NB*HW];
__device__ float g_c1  [NB*C1*HW];
__device__ float g_c2  [NB*C2*HW];
__device__ float g_gauss[KS];
__device__ int   g_max[NB];              // float bits, values >= 0
__device__ float g_stats1[2*C1];         // sum, sumsq
__device__ float g_stats2[2*C2];

// ---------------- concat copy, software-pipelined through the chain ----------------
// dst[i + (i/PER_B)*DSKIP] = src[i], i in [0, COPY_N). Each thread: up to D
// independent streaming float4 loads in the PROLOGUE (latency hidden behind the
// kernel's compute), D streaming stores in the EPILOGUE.
#define COPY_N  (NB*CSP*HW/4)            // 20,570,112 float4s
#define PER_B   (CSP*HW/4)               // 5,142,528
#define DSKIP   ((COUT-CSP)*HW/4)        // 214,272

// shares (sum == COPY_N); capacity D*threads >= share verified per kernel.
#define S_HIST  1500000
#define S_BLX   3200000
#define S_BLY   3200000
#define S_DOWN  850000
#define S_CV1   6000000
#define S_CV2   2500000
#define S_OUT   (COPY_N - S_HIST - S_BLX - S_BLY - S_DOWN - S_CV1 - S_CV2)  // 3,320,112
#define O_HIST  0
#define O_BLX   (O_HIST + S_HIST)
#define O_BLY   (O_BLX + S_BLX)
#define O_DOWN  (O_BLY + S_BLY)
#define O_CV1   (O_DOWN + S_DOWN)
#define O_CV2   (O_CV1 + S_CV1)
#define O_OUT   (O_CV2 + S_CV2)

template<int D>
struct CopyCtx { float4 v[D]; int idx[D]; };

template<int D>
__device__ __forceinline__ void copy_pro(const float4* __restrict__ src,
                                         int start, int count, CopyCtx<D>& c) {
    int tid = ((blockIdx.y*gridDim.x + blockIdx.x)*blockDim.x) + threadIdx.x;
    int nth = gridDim.x*gridDim.y*blockDim.x;
    int end = start + count;
    #pragma unroll
    for (int k = 0; k < D; k++) {
        int i = start + tid + k*nth;
        c.idx[k] = (i < end) ? i : -1;
    }
    #pragma unroll
    for (int k = 0; k < D; k++)
        if (c.idx[k] >= 0) c.v[k] = __ldcs(src + c.idx[k]);
}

template<int D>
__device__ __forceinline__ void copy_epi(float4* __restrict__ dst, const CopyCtx<D>& c) {
    #pragma unroll
    for (int k = 0; k < D; k++)
        if (c.idx[k] >= 0) {
            int b = c.idx[k] / PER_B;
            __stcs(dst + c.idx[k] + b*DSKIP, c.v[k]);
        }
}

// hist: atomics into g_hist (zeroed by previous launch's k_out / static init).
// Also: gaussian weights + zero stats1/stats2/max (all read only by LATER nodes).
__global__ void k_hist(const float* __restrict__ pts, int n,
                       const float4* __restrict__ cs, float4* __restrict__ cd) {
    CopyCtx<4> cc; copy_pro<4>(cs, O_HIST, S_HIST, cc);
    int i = blockIdx.x*blockDim.x + threadIdx.x;
    if (i < KS) {
        const float sig = 6.25f;
        float s = 0.f;
        for (int k = 0; k < KS; k++) {
            float c = (float)(k - RAD);
            s += expf(-c*c/(2.f*sig*sig));
        }
        float c = (float)(i - RAD);
        g_gauss[i] = expf(-c*c/(2.f*sig*sig)) / s;
    }
    if (i < NB)   g_max[i] = 0;
    if (i < 2*C1) g_stats1[i] = 0.f;
    if (i < 2*C2) g_stats2[i] = 0.f;
    if (i < n) {
        const float* p = pts + (size_t)i*5;
        int b = (int)p[0];
        int x = (int)__fdiv_rn(p[1] - 0.0f,  0.16f);
        int y = (int)__fdiv_rn(p[2] + 39.68f, 0.16f);
        x = min(max(x, 0), NXg-1);
        y = min(max(y, 0), NYg-1);
        atomicAdd(&g_hist[(b*NYg + y)*NXg + x], 1.0f);
    }
    copy_epi<4>(cd, cc);
}

__global__ void k_blur_x(const float4* __restrict__ cs, float4* __restrict__ cd) {
    CopyCtx<4> cc; copy_pro<4>(cs, O_BLX, S_BLX, cc);
    int i = blockIdx.x*blockDim.x + threadIdx.x;
    if (i < GTOT) {
        int x = i % NXg;
        int row = i / NXg;  // b*NYg + y
        float acc = 0.f;
        #pragma unroll
        for (int k = 0; k < KS; k++) {
            int xx = x + k - RAD;
            if (xx >= 0 && xx < NXg)
                acc += g_gauss[k] * g_hist[row*NXg + xx];
        }
        g_tmp[i] = acc;
    }
    copy_epi<4>(cd, cc);
}

// blur in y + fused per-batch max (GTOT divisible by 256 -> block never straddles batch)
__global__ void k_blur_y(const float4* __restrict__ cs, float4* __restrict__ cd) {
    CopyCtx<4> cc; copy_pro<4>(cs, O_BLY, S_BLY, cc);
    int i = blockIdx.x*blockDim.x + threadIdx.x;
    int x = i % NXg;
    int y = (i / NXg) % NYg;
    int b = i / (NXg*NYg);
    float acc = 0.f;
    #pragma unroll
    for (int k = 0; k < KS; k++) {
        int yy = y + k - RAD;
        if (yy >= 0 && yy < NYg)
            acc += g_gauss[k] * g_tmp[(b*NYg + yy)*NXg + x];
    }
    g_hist[i] = acc;   // blurred result back into g_hist

    __shared__ float sm[256];
    sm[threadIdx.x] = acc; __syncthreads();
    for (int s = 128; s > 0; s >>= 1) {
        if (threadIdx.x < s) sm[threadIdx.x] = fmaxf(sm[threadIdx.x], sm[threadIdx.x+s]);
        __syncthreads();
    }
    if (threadIdx.x == 0) atomicMax(&g_max[b], __float_as_int(sm[0]));
    copy_epi<4>(cd, cc);
}

// jax.image.resize 'linear' antialias=True, 2x downsample:
// taps at 2i-1..2i+2 with weights [1,3,3,1], edge-clipped + renormalized.
__device__ __forceinline__ void taps4(int i, int n, int* j, float* w) {
    const float base[4] = {1.f, 3.f, 3.f, 1.f};
    float s = 0.f;
    #pragma unroll
    for (int k = 0; k < 4; k++) {
        int jj = 2*i - 1 + k;
        j[k] = jj;
        if (jj >= 0 && jj < n) { w[k] = base[k]; s += base[k]; }
        else w[k] = 0.f;
    }
    #pragma unroll
    for (int k = 0; k < 4; k++) w[k] /= s;
}

__global__ void k_down(const float4* __restrict__ cs, float4* __restrict__ cd) {
    CopyCtx<4> cc; copy_pro<4>(cs, O_DOWN, S_DOWN, cc);
    int i = blockIdx.x*blockDim.x + threadIdx.x;
    if (i < NB*HW) {
        int x = i % Wc;
        int y = (i / Wc) % Hc;
        int b = i / HW;
        int jy[4], jx[4]; float wy[4], wx[4];
        taps4(y, NYg, jy, wy);
        taps4(x, NXg, jx, wx);
        float acc = 0.f;
        #pragma unroll
        for (int a = 0; a < 4; a++) {
            if (wy[a] != 0.f) {
                float r = 0.f;
                #pragma unroll
                for (int c = 0; c < 4; c++) {
                    if (wx[c] != 0.f)
                        r += wx[c] * g_hist[(b*NYg + jy[a])*NXg + jx[c]];
                }
                acc += wy[a] * r;
            }
        }
        float mx = __int_as_float(g_max[b]);
        g_dm[i] = (mx > 0.f) ? acc / mx : acc;
    }
    copy_epi<4>(cd, cc);
}

__global__ void k_conv1(const float* __restrict__ w1,
                        const float4* __restrict__ cs, float4* __restrict__ cd) {
    CopyCtx<4> cc; copy_pro<4>(cs, O_CV1, S_CV1, cc);
    int bc = blockIdx.y;                 // b*C1 + c
    int b = bc / C1, c = bc % C1;
    int hw = blockIdx.x*blockDim.x + threadIdx.x;
    float v = 0.f;
    if (hw < HW) {
        int x = hw % Wc, y = hw / Wc;
        const float* wp = w1 + c*9;
        const float* in = g_dm + b*HW;
        #pragma unroll
        for (int dy = 0; dy < 3; dy++) {
            int yy = y + dy - 1;
            if (yy < 0 || yy >= Hc) continue;
            #pragma unroll
            for (int dx = 0; dx < 3; dx++) {
                int xx = x + dx - 1;
                if (xx < 0 || xx >= Wc) continue;
                v = fmaf(__ldg(&wp[dy*3+dx]), in[yy*Wc+xx], v);
            }
        }
        g_c1[bc*HW + hw] = v;
    }
    __shared__ float s1[256], s2[256];
    float vv = (hw < HW) ? v : 0.f;
    s1[threadIdx.x] = vv; s2[threadIdx.x] = vv*vv;
    __syncthreads();
    for (int s = 128; s > 0; s >>= 1) {
        if (threadIdx.x < s) { s1[threadIdx.x] += s1[threadIdx.x+s]; s2[threadIdx.x] += s2[threadIdx.x+s]; }
        __syncthreads();
    }
    if (threadIdx.x == 0) {
        atomicAdd(&g_stats1[c], s1[0]);
        atomicAdd(&g_stats1[C1 + c], s2[0]);
    }
    copy_epi<4>(cd, cc);
}

// conv2 with BN1+ReLU applied inline to raw conv1 output; small copy share (D=2).
__global__ void k_conv2(const float* __restrict__ w2,
                        const float* __restrict__ gamma1, const float* __restrict__ beta1,
                        const float4* __restrict__ cs, float4* __restrict__ cd) {
    CopyCtx<2> cc; copy_pro<2>(cs, O_CV2, S_CV2, cc);
    int bc = blockIdx.y;                 // b*C2 + co
    int b = bc / C2, co = bc % C2;
    __shared__ float ws[C1*9];
    __shared__ float sc1[C1], sh1[C1];
    if (threadIdx.x < C1*9) ws[threadIdx.x] = w2[co*C1*9 + threadIdx.x];
    if (threadIdx.x < C1) {
        int c = threadIdx.x;
        float mean = g_stats1[c] / (float)NBN;
        float var  = g_stats1[C1+c] / (float)NBN - mean*mean;
        float s    = gamma1[c] * rsqrtf(var + 1e-3f);
        sc1[c] = s; sh1[c] = beta1[c] - mean*s;
    }
    __syncthreads();
    int hw = blockIdx.x*blockDim.x + threadIdx.x;
    float v = 0.f;
    if (hw < HW) {
        int x = hw % Wc, y = hw / Wc;
        #pragma unroll
        for (int ci = 0; ci < C1; ci++) {
            const float* in = g_c1 + (b*C1 + ci)*HW;
            const float* wp = ws + ci*9;
            float a = sc1[ci], s0 = sh1[ci];
            #pragma unroll
            for (int dy = 0; dy < 3; dy++) {
                int yy = y + dy - 1;
                if (yy < 0 || yy >= Hc) continue;
                #pragma unroll
                for (int dx = 0; dx < 3; dx++) {
                    int xx = x + dx - 1;
                    if (xx < 0 || xx >= Wc) continue;
                    float t = fmaxf(fmaf(in[yy*Wc+xx], a, s0), 0.f);
                    v = fmaf(wp[dy*3+dx], t, v);
                }
            }
        }
        g_c2[bc*HW + hw] = v;
    }
    __shared__ float s1[256], s2[256];
    float vv = (hw < HW) ? v : 0.f;
    s1[threadIdx.x] = vv; s2[threadIdx.x] = vv*vv;
    __syncthreads();
    for (int s = 128; s > 0; s >>= 1) {
        if (threadIdx.x < s) { s1[threadIdx.x] += s1[threadIdx.x+s]; s2[threadIdx.x] += s2[threadIdx.x+s]; }
        __syncthreads();
    }
    if (threadIdx.x == 0) {
        atomicAdd(&g_stats2[co], s1[0]);
        atomicAdd(&g_stats2[C2 + co], s2[0]);
    }
    copy_epi<2>(cd, cc);
}

// BN2 affine per-block, relu, scatter into concat slot.
// Also zeroes g_hist for the NEXT replay (g_hist's last reader, k_down, already ran).
__global__ void k_out(float* __restrict__ out,
                      const float* __restrict__ gamma, const float* __restrict__ beta,
                      const float4* __restrict__ cs, float4* __restrict__ cd) {
    CopyCtx<4> cc; copy_pro<4>(cs, O_OUT, S_OUT, cc);
    __shared__ float sc[C2], sh[C2];
    if (threadIdx.x < C2) {
        int c = threadIdx.x;
        float mean = g_stats2[c] / (float)NBN;
        float var  = g_stats2[C2+c] / (float)NBN - mean*mean;
        float s    = gamma[c] * rsqrtf(var + 1e-3f);
        sc[c] = s; sh[c] = beta[c] - mean*s;
    }
    __syncthreads();
    int i = blockIdx.x*blockDim.x + threadIdx.x;
    if (i < NB*C2*HW) {
        int hw = i % HW;
        int c  = (i / HW) % C2;
        int b  = i / (C2*HW);
        float v = fmaxf(fmaf(g_c2[i], sc[c], sh[c]), 0.f);
        out[((size_t)b*COUT + CSP + c)*HW + hw] = v;
    }
    if (i < GTOT) g_hist[i] = 0.f;       // leave zeroed for next launch
    copy_epi<4>(cd, cc);
}

extern "C" void kernel_launch(void* const* d_in, const int* in_sizes, int n_in,
                              void* d_out, int out_size) {
    const float* spatial = (const float*)d_in[0];
    const float* points  = (const float*)d_in[1];
    const float* w1      = (const float*)d_in[2];
    const float* gamma1  = (const float*)d_in[3];
    const float* beta1   = (const float*)d_in[4];
    const float* w2      = (const float*)d_in[5];
    const float* gamma2  = (const float*)d_in[6];
    const float* beta2   = (const float*)d_in[7];
    float* out = (float*)d_out;
    int npts = in_sizes[1] / 5;

    const float4* cs = (const float4*)spatial;
    float4* cd = (float4*)out;

    // hist grid padded so copy capacity (4*threads >= S_HIST) holds for any npts
    int gh = (npts + 255)/256;
    int gmin = (S_HIST + 4*256 - 1)/(4*256);
    if (gh < gmin) gh = gmin;

    k_hist  <<<gh, 256>>>(points, npts, cs, cd);
    k_blur_x<<<(GTOT + 255)/256, 256>>>(cs, cd);
    k_blur_y<<<GTOT/256, 256>>>(cs, cd);
    k_down  <<<(NB*HW + 255)/256, 256>>>(cs, cd);
    { dim3 g((HW + 255)/256, NB*C1); k_conv1<<<g, 256>>>(w1, cs, cd); }
    { dim3 g((HW + 255)/256, NB*C2); k_conv2<<<g, 256>>>(w2, gamma1, beta1, cs, cd); }
    k_out   <<<(NB*C2*HW + 255)/256, 256>>>(out, gamma2, beta2, cs, cd);
}